// round 12
// baseline (speedup 1.0000x reference)
#include <cuda_runtime.h>
#include <cuda_bf16.h>

// Problem constants (match reference_code)
#define N_L   90
#define N_B   20
#define N_MU  46
#define N_LF  51
#define N_OUTK (N_LF - N_MU + 1)          // 6
#define NBINS (N_L * N_B * N_MU)          // 82800
#define N_LB  (N_L * N_B)                 // 1800
#define NOUT  (N_LB * N_OUTK)             // 10800

#define MN0  (-90.0f)
#define MN1  (-12.0f)
#define MN2  (7.0f)

#define THREADS        256
#define PER_THREAD     8
#define PART_PER_BLOCK (THREADS * PER_THREAD)   // 2048
#define EPI_MAX        8                        // last-8-blocks epilogue

// Zero-initialized at module load; re-zeroed by the fused epilogue (each
// epilogue thread zeroes exactly the 46-bin slice it alone convolved).
// Counters reset by the last epilogue block. Deterministic per replay.
static __device__ float g_hist[NBINS];
static __device__ unsigned g_done = 0;   // hist-blocks-finished counter
static __device__ unsigned g_fin  = 0;   // epilogue-blocks-finished counter

__device__ __forceinline__ int bin_of(float x, float y, float z,
                                      float idx0, float idx1, float idx2) {
    int i0 = __float2int_rn((x - MN0) * idx0);
    int i1 = __float2int_rn((y - MN1) * idx1);
    int i2 = __float2int_rn((z - MN2) * idx2);
    bool ok = (unsigned)i0 < (unsigned)N_L &&
              (unsigned)i1 < (unsigned)N_B &&
              (unsigned)i2 < (unsigned)N_MU;
    return ok ? (i0 * (N_B * N_MU) + i1 * N_MU + i2) : -1;
}

__device__ __forceinline__ void red_add(int b, float m) {
    if (b >= 0) {
        // No-return global reduction (REDG), not ATOMG.
        asm volatile("red.global.add.f32 [%0], %1;"
                     :: "l"(&g_hist[b]), "f"(m) : "memory");
    }
}

__device__ __forceinline__ unsigned acq_load(const unsigned* p) {
    unsigned v;
    asm volatile("ld.acquire.gpu.global.u32 %0, [%1];" : "=r"(v) : "l"(p) : "memory");
    return v;
}

// Fused kernel. Hist phase = R8/R10 measured best (smem-staged coalesced
// loads, stride-3 LDS, uninterrupted RED burst). __launch_bounds__(256,7)
// pins regs at <=36 so the cold epilogue cannot deflate hist occupancy
// (the R9 failure mode); epilogue register pressure spills to local instead.
__global__ void __launch_bounds__(THREADS, 7)
hist_fused_kernel(const float* __restrict__ lbm,
                  const float* __restrict__ mass,
                  const float* __restrict__ lf,
                  float* __restrict__ out,
                  int n) {
    __shared__ float sc[PART_PER_BLOCK * 3];   // 24 KB coords
    __shared__ float sm[PART_PER_BLOCK];       //  8 KB masses
    __shared__ unsigned s_ticket;

    const float dx0 = (90.0f - (-90.0f)) / (float)(N_L - 1);
    const float dx1 = (12.0f - (-12.0f)) / (float)(N_B - 1);
    const float dx2 = (16.0f - 7.0f) / (float)(N_MU - 1);
    const float idx0 = 1.0f / dx0;
    const float idx1 = 1.0f / dx1;
    const float idx2 = 1.0f / dx2;

    const int t   = threadIdx.x;
    const int bs  = blockIdx.x * PART_PER_BLOCK;        // block start particle
    const int cnt = min(PART_PER_BLOCK, n - bs);

    // ---------------- histogram phase (R8 measured best) ----------------
    if (cnt == PART_PER_BLOCK) {
        const float4* c4 = (const float4*)(lbm + (size_t)bs * 3);
        float4* s4 = (float4*)sc;
#pragma unroll
        for (int i = 0; i < 6; i++) s4[t + THREADS * i] = c4[t + THREADS * i];
        const float4* m4 = (const float4*)(mass + bs);
        float4* sm4 = (float4*)sm;
        sm4[t + THREADS * 0] = m4[t + THREADS * 0];
        sm4[t + THREADS * 1] = m4[t + THREADS * 1];
    } else {
        for (int i = t; i < cnt * 3; i += THREADS) sc[i] = lbm[(size_t)bs * 3 + i];
        for (int i = t; i < cnt;     i += THREADS) sm[i] = mass[bs + i];
    }
    __syncthreads();

    if (cnt == PART_PER_BLOCK) {
        int   b[PER_THREAD];
        float m[PER_THREAD];
#pragma unroll
        for (int j = 0; j < PER_THREAD; j++) {
            int p = t + THREADS * j;                    // bank-conflict-free (stride 3)
            b[j] = bin_of(sc[3 * p + 0], sc[3 * p + 1], sc[3 * p + 2],
                          idx0, idx1, idx2);
            m[j] = sm[p];
        }
        // Uninterrupted RED burst.
#pragma unroll
        for (int j = 0; j < PER_THREAD; j++) red_add(b[j], m[j]);
    } else {
#pragma unroll
        for (int j = 0; j < PER_THREAD; j++) {
            int p = t + THREADS * j;
            if (p < cnt) {
                int bb = bin_of(sc[3 * p + 0], sc[3 * p + 1], sc[3 * p + 2],
                                idx0, idx1, idx2);
                red_add(bb, sm[p]);
            }
        }
    }

    // ---------------- decoupled epilogue handoff ----------------
    __syncthreads();
    const unsigned grid = gridDim.x;
    if (t == 0) {
        __threadfence();                     // publish this block's REDs
        s_ticket = atomicAdd(&g_done, 1u);   // ticket = finish order
    }
    __syncthreads();
    const unsigned ticket = s_ticket;
    const unsigned nepi = (grid < EPI_MAX) ? grid : EPI_MAX;
    if (ticket < grid - nepi) return;        // not an epilogue block

    const unsigned rank = ticket - (grid - nepi);

    // Wait until ALL hist blocks have published their REDs.
    if (t == 0) {
        while (acq_load(&g_done) < grid) __nanosleep(64);
    }
    __syncthreads();
    __threadfence();                         // acquire: hist now complete

    // ---------------- conv + zero: one (l,b) per epilogue thread ----------------
    // Reuse hist smem (sc) for the LF table; no extra static smem.
    float* s_lf = sc;
    if (t < N_LF) s_lf[t] = lf[t];
    __syncthreads();

    const int id     = (int)rank * THREADS + t;
    const int stride = (int)nepi * THREADS;
    for (int lb = id; lb < N_LB; lb += stride) {
        float* h = &g_hist[lb * N_MU];
        float acc[N_OUTK];
#pragma unroll
        for (int k = 0; k < N_OUTK; k++) acc[k] = 0.0f;
#pragma unroll
        for (int i = 0; i < N_MU; i++) {
            float hv = __ldcg(&h[i]);
#pragma unroll
            for (int k = 0; k < N_OUTK; k++) {
                acc[k] = fmaf(hv, s_lf[k + (N_MU - 1) - i], acc[k]);
            }
        }
#pragma unroll
        for (int k = 0; k < N_OUTK; k++) out[lb * N_OUTK + k] = acc[k];
        // Zero the slice only THIS thread read — no cross-thread hazard.
#pragma unroll
        for (int i = 0; i < N_MU; i++) h[i] = 0.0f;
    }

    // Last epilogue block to finish resets counters for the next replay.
    __syncthreads();
    if (t == 0) {
        __threadfence();
        unsigned f = atomicAdd(&g_fin, 1u);
        if (f == nepi - 1) {                 // everyone else is fully done
            g_done = 0;
            g_fin  = 0;
        }
    }
}

extern "C" void kernel_launch(void* const* d_in, const int* in_sizes, int n_in,
                              void* d_out, int out_size) {
    const float* lbm  = (const float*)d_in[0];   // [N,3] float32
    const float* mass = (const float*)d_in[1];   // [N]   float32
    const float* lf   = (const float*)d_in[2];   // [51]  float32
    float* out = (float*)d_out;                  // [90,20,6] float32

    int n = in_sizes[1];
    int grid = (n + PART_PER_BLOCK - 1) / PART_PER_BLOCK;
    if (grid < 1) grid = 1;

    hist_fused_kernel<<<grid, THREADS>>>(lbm, mass, lf, out, n);
}

// round 13
// speedup vs baseline: 1.2691x; 1.2691x over previous
#include <cuda_runtime.h>
#include <cuda_bf16.h>

// Problem constants (match reference_code)
#define N_L   90
#define N_B   20
#define N_MU  46
#define N_LF  51
#define N_OUTK (N_LF - N_MU + 1)          // 6
#define NBINS (N_L * N_B * N_MU)          // 82800
#define N_LB  (N_L * N_B)                 // 1800
#define NOUT  (N_LB * N_OUTK)             // 10800

#define MN0  (-90.0f)
#define MN1  (-12.0f)
#define MN2  (7.0f)

#define THREADS        256
#define PER_THREAD     8
#define PART_PER_BLOCK (THREADS * PER_THREAD)   // 2048

#define WARPS_PER_CONV_BLOCK 8
#define CONV_BLOCKS ((N_LB + WARPS_PER_CONV_BLOCK - 1) / WARPS_PER_CONV_BLOCK) // 225

// Zero-initialized at module load; re-zeroed by conv_zero_kernel (each warp
// zeroes exactly the 46-bin slice it alone consumed). Deterministic per replay.
static __device__ float g_hist[NBINS];

__device__ __forceinline__ int bin_of(float x, float y, float z,
                                      float idx0, float idx1, float idx2) {
    int i0 = __float2int_rn((x - MN0) * idx0);
    int i1 = __float2int_rn((y - MN1) * idx1);
    int i2 = __float2int_rn((z - MN2) * idx2);
    bool ok = (unsigned)i0 < (unsigned)N_L &&
              (unsigned)i1 < (unsigned)N_B &&
              (unsigned)i2 < (unsigned)N_MU;
    return ok ? (i0 * (N_B * N_MU) + i1 * N_MU + i2) : -1;
}

__device__ __forceinline__ void red_add(int b, float m) {
    if (b >= 0) {
        // No-return global reduction (REDG), not ATOMG. Fire-and-forget:
        // blocks retire while REDs drain (critical — do NOT fence).
        asm volatile("red.global.add.f32 [%0], %1;"
                     :: "l"(&g_hist[b]), "f"(m) : "memory");
    }
}

// ============ hist kernel: byte-identical to the R8/R10 measured best ============
// Block owns 2048 contiguous particles. Coords AND masses staged through smem
// with fully-coalesced float4 loads; compute phase is LDS -> 8 bin computes ->
// 8 back-to-back REDs (no LDG in the dependency chain). (Measured ~132.7us.)
__global__ void __launch_bounds__(THREADS)
hist_kernel(const float* __restrict__ lbm,
            const float* __restrict__ mass,
            int n) {
    __shared__ float sc[PART_PER_BLOCK * 3];   // 24 KB coords
    __shared__ float sm[PART_PER_BLOCK];       //  8 KB masses

    const float dx0 = (90.0f - (-90.0f)) / (float)(N_L - 1);
    const float dx1 = (12.0f - (-12.0f)) / (float)(N_B - 1);
    const float dx2 = (16.0f - 7.0f) / (float)(N_MU - 1);
    const float idx0 = 1.0f / dx0;
    const float idx1 = 1.0f / dx1;
    const float idx2 = 1.0f / dx2;

    const int t   = threadIdx.x;
    const int bs  = blockIdx.x * PART_PER_BLOCK;        // block start particle
    const int cnt = min(PART_PER_BLOCK, n - bs);

    if (cnt == PART_PER_BLOCK) {
        const float4* c4 = (const float4*)(lbm + (size_t)bs * 3);
        float4* s4 = (float4*)sc;
#pragma unroll
        for (int i = 0; i < 6; i++) s4[t + THREADS * i] = c4[t + THREADS * i];
        const float4* m4 = (const float4*)(mass + bs);
        float4* sm4 = (float4*)sm;
        sm4[t + THREADS * 0] = m4[t + THREADS * 0];
        sm4[t + THREADS * 1] = m4[t + THREADS * 1];
    } else {
        for (int i = t; i < cnt * 3; i += THREADS) sc[i] = lbm[(size_t)bs * 3 + i];
        for (int i = t; i < cnt;     i += THREADS) sm[i] = mass[bs + i];
    }
    __syncthreads();

    if (cnt == PART_PER_BLOCK) {
        int   b[PER_THREAD];
        float m[PER_THREAD];
#pragma unroll
        for (int j = 0; j < PER_THREAD; j++) {
            int p = t + THREADS * j;                    // bank-conflict-free (stride 3)
            b[j] = bin_of(sc[3 * p + 0], sc[3 * p + 1], sc[3 * p + 2],
                          idx0, idx1, idx2);
            m[j] = sm[p];
        }
        // Uninterrupted RED burst.
#pragma unroll
        for (int j = 0; j < PER_THREAD; j++) red_add(b[j], m[j]);
    } else {
#pragma unroll
        for (int j = 0; j < PER_THREAD; j++) {
            int p = t + THREADS * j;
            if (p < cnt) {
                int bb = bin_of(sc[3 * p + 0], sc[3 * p + 1], sc[3 * p + 2],
                                idx0, idx1, idx2);
                red_add(bb, sm[p]);
            }
        }
    }
}

// ============ conv+zero: one WARP per (l,b) pair ============
// Lanes load h[lane] and (lane<14) h[lane+32]; per-lane partials for the 6
// outputs; 6 butterfly reductions; lane 0 writes 6 floats; warp zeroes its
// own slice. 225 blocks -> much better latency hiding than 57.
__global__ void __launch_bounds__(THREADS)
conv_zero_kernel(const float* __restrict__ lf, float* __restrict__ out) {
    __shared__ float s_lf[N_LF];
    const int t = threadIdx.x;

    cudaGridDependencySynchronize();   // PDL dependency point

    if (t < N_LF) s_lf[t] = lf[t];
    __syncthreads();

    const int lane = t & 31;
    const int lb   = blockIdx.x * WARPS_PER_CONV_BLOCK + (t >> 5);
    if (lb >= N_LB) return;

    float* h = &g_hist[lb * N_MU];
    const float v0 = h[lane];                               // lanes 0..31
    const float v1 = (lane < N_MU - 32) ? h[lane + 32] : 0.0f;  // lanes 0..13

    float p[N_OUTK];
#pragma unroll
    for (int k = 0; k < N_OUTK; k++) {
        // out[k] = sum_i h[i] * lf[k + 45 - i]
        float a = s_lf[k + (N_MU - 1) - lane];              // i = lane
        float b = (lane < N_MU - 32) ? s_lf[k + (N_MU - 1) - 32 - lane] : 0.0f;
        p[k] = fmaf(v0, a, v1 * b);
    }
    // Butterfly reductions (all lanes end with the total).
#pragma unroll
    for (int off = 16; off > 0; off >>= 1) {
#pragma unroll
        for (int k = 0; k < N_OUTK; k++) {
            p[k] += __shfl_xor_sync(0xFFFFFFFFu, p[k], off);
        }
    }
    if (lane < N_OUTK) out[lb * N_OUTK + lane] = p[lane];   // broadcast via shfl idx
    // (each lane has every total; lane k writes p[k]? p is per-lane array ->
    //  all lanes hold identical totals after butterfly, so lane k's p[k] is
    //  the correct k-th output.)

    // Zero the slice this warp alone read.
    h[lane] = 0.0f;
    if (lane < N_MU - 32) h[lane + 32] = 0.0f;
}

extern "C" void kernel_launch(void* const* d_in, const int* in_sizes, int n_in,
                              void* d_out, int out_size) {
    const float* lbm  = (const float*)d_in[0];   // [N,3] float32
    const float* mass = (const float*)d_in[1];   // [N]   float32
    const float* lf   = (const float*)d_in[2];   // [51]  float32
    float* out = (float*)d_out;                  // [90,20,6] float32

    int n = in_sizes[1];
    int grid = (n + PART_PER_BLOCK - 1) / PART_PER_BLOCK;
    if (grid < 1) grid = 1;

    hist_kernel<<<grid, THREADS>>>(lbm, mass, n);

    // PDL launch: conv_zero prelaunches while hist drains.
    {
        cudaLaunchConfig_t cfg = {};
        cfg.gridDim  = dim3(CONV_BLOCKS, 1, 1);
        cfg.blockDim = dim3(THREADS, 1, 1);
        cfg.dynamicSmemBytes = 0;
        cfg.stream = 0;
        cudaLaunchAttribute attrs[1];
        attrs[0].id = cudaLaunchAttributeProgrammaticStreamSerialization;
        attrs[0].val.programmaticStreamSerializationAllowed = 1;
        cfg.attrs = attrs;
        cfg.numAttrs = 1;
        cudaLaunchKernelEx(&cfg, conv_zero_kernel, lf, out);
    }
}

// round 14
// speedup vs baseline: 1.2741x; 1.0039x over previous
#include <cuda_runtime.h>
#include <cuda_bf16.h>

// Problem constants (match reference_code)
#define N_L   90
#define N_B   20
#define N_MU  46
#define N_LF  51
#define N_OUTK (N_LF - N_MU + 1)          // 6
#define NBINS (N_L * N_B * N_MU)          // 82800
#define N_LB  (N_L * N_B)                 // 1800
#define NOUT  (N_LB * N_OUTK)             // 10800

#define MN0  (-90.0f)
#define MN1  (-12.0f)
#define MN2  (7.0f)

#define THREADS        256
#define PER_THREAD     8
#define PART_PER_BLOCK (THREADS * PER_THREAD)   // 2048
#define HALF_PART      (PART_PER_BLOCK / 2)     // 1024

#define WARPS_PER_CONV_BLOCK 8
#define CONV_BLOCKS ((N_LB + WARPS_PER_CONV_BLOCK - 1) / WARPS_PER_CONV_BLOCK) // 225

// Zero-initialized at module load; re-zeroed by conv_zero_kernel (each warp
// zeroes exactly the 46-bin slice it alone consumed). Deterministic per replay.
static __device__ float g_hist[NBINS];

__device__ __forceinline__ int bin_of(float x, float y, float z,
                                      float idx0, float idx1, float idx2) {
    int i0 = __float2int_rn((x - MN0) * idx0);
    int i1 = __float2int_rn((y - MN1) * idx1);
    int i2 = __float2int_rn((z - MN2) * idx2);
    bool ok = (unsigned)i0 < (unsigned)N_L &&
              (unsigned)i1 < (unsigned)N_B &&
              (unsigned)i2 < (unsigned)N_MU;
    return ok ? (i0 * (N_B * N_MU) + i1 * N_MU + i2) : -1;
}

__device__ __forceinline__ void red_add(int b, float m) {
    if (b >= 0) {
        // No-return global reduction (REDG), not ATOMG. Fire-and-forget:
        // blocks retire while REDs drain (critical — do NOT fence).
        asm volatile("red.global.add.f32 [%0], %1;"
                     :: "l"(&g_hist[b]), "f"(m) : "memory");
    }
}

// Block owns 2048 contiguous particles, staged via coalesced float4 LDG/STS.
// Compute phase: each thread owns 4 CONSECUTIVE particles (x2 halves) so the
// smem reads are 3x LDS.128 coords + 1x LDS.128 masses per 4 particles
// (conflict-free: 48B thread stride cycles all 32 banks per 8-thread phase).
// LSU ops/thread drop 56 -> 32, freeing issue slots for the RED drain.
__global__ void __launch_bounds__(THREADS)
hist_kernel(const float* __restrict__ lbm,
            const float* __restrict__ mass,
            int n) {
    __shared__ float sc[PART_PER_BLOCK * 3];   // 24 KB coords
    __shared__ float sm[PART_PER_BLOCK];       //  8 KB masses

    const float dx0 = (90.0f - (-90.0f)) / (float)(N_L - 1);
    const float dx1 = (12.0f - (-12.0f)) / (float)(N_B - 1);
    const float dx2 = (16.0f - 7.0f) / (float)(N_MU - 1);
    const float idx0 = 1.0f / dx0;
    const float idx1 = 1.0f / dx1;
    const float idx2 = 1.0f / dx2;

    const int t   = threadIdx.x;
    const int bs  = blockIdx.x * PART_PER_BLOCK;        // block start particle
    const int cnt = min(PART_PER_BLOCK, n - bs);

    if (cnt == PART_PER_BLOCK) {
        const float4* c4 = (const float4*)(lbm + (size_t)bs * 3);
        float4* s4 = (float4*)sc;
#pragma unroll
        for (int i = 0; i < 6; i++) s4[t + THREADS * i] = c4[t + THREADS * i];
        const float4* m4 = (const float4*)(mass + bs);
        float4* sm4 = (float4*)sm;
        sm4[t + THREADS * 0] = m4[t + THREADS * 0];
        sm4[t + THREADS * 1] = m4[t + THREADS * 1];
    } else {
        for (int i = t; i < cnt * 3; i += THREADS) sc[i] = lbm[(size_t)bs * 3 + i];
        for (int i = t; i < cnt;     i += THREADS) sm[i] = mass[bs + i];
    }
    __syncthreads();

    if (cnt == PART_PER_BLOCK) {
#pragma unroll
        for (int half = 0; half < 2; half++) {
            const int p0 = 4 * t + half * HALF_PART;   // 4 consecutive particles
            // 12 consecutive coord floats: 3x LDS.128 (16B-aligned: 48t|16).
            float4 a = *(const float4*)&sc[3 * p0 + 0];
            float4 b = *(const float4*)&sc[3 * p0 + 4];
            float4 c = *(const float4*)&sc[3 * p0 + 8];
            float4 m = *(const float4*)&sm[p0];        // 4 masses: 1x LDS.128

            int b0 = bin_of(a.x, a.y, a.z, idx0, idx1, idx2);
            int b1 = bin_of(a.w, b.x, b.y, idx0, idx1, idx2);
            int b2 = bin_of(b.z, b.w, c.x, idx0, idx1, idx2);
            int b3 = bin_of(c.y, c.z, c.w, idx0, idx1, idx2);
            // Uninterrupted RED burst.
            red_add(b0, m.x);
            red_add(b1, m.y);
            red_add(b2, m.z);
            red_add(b3, m.w);
        }
    } else {
#pragma unroll
        for (int j = 0; j < PER_THREAD; j++) {
            int p = t + THREADS * j;
            if (p < cnt) {
                int bb = bin_of(sc[3 * p + 0], sc[3 * p + 1], sc[3 * p + 2],
                                idx0, idx1, idx2);
                red_add(bb, sm[p]);
            }
        }
    }
}

// conv+zero: one WARP per (l,b) pair (measured best epilogue, 5.8us).
__global__ void __launch_bounds__(THREADS)
conv_zero_kernel(const float* __restrict__ lf, float* __restrict__ out) {
    __shared__ float s_lf[N_LF];
    const int t = threadIdx.x;

    cudaGridDependencySynchronize();   // PDL dependency point

    if (t < N_LF) s_lf[t] = lf[t];
    __syncthreads();

    const int lane = t & 31;
    const int lb   = blockIdx.x * WARPS_PER_CONV_BLOCK + (t >> 5);
    if (lb >= N_LB) return;

    float* h = &g_hist[lb * N_MU];
    const float v0 = h[lane];                                   // lanes 0..31
    const float v1 = (lane < N_MU - 32) ? h[lane + 32] : 0.0f;  // lanes 0..13

    float p[N_OUTK];
#pragma unroll
    for (int k = 0; k < N_OUTK; k++) {
        float a = s_lf[k + (N_MU - 1) - lane];
        float b = (lane < N_MU - 32) ? s_lf[k + (N_MU - 1) - 32 - lane] : 0.0f;
        p[k] = fmaf(v0, a, v1 * b);
    }
#pragma unroll
    for (int off = 16; off > 0; off >>= 1) {
#pragma unroll
        for (int k = 0; k < N_OUTK; k++) {
            p[k] += __shfl_xor_sync(0xFFFFFFFFu, p[k], off);
        }
    }
    if (lane < N_OUTK) out[lb * N_OUTK + lane] = p[lane];

    // Zero the slice this warp alone read.
    h[lane] = 0.0f;
    if (lane < N_MU - 32) h[lane + 32] = 0.0f;
}

extern "C" void kernel_launch(void* const* d_in, const int* in_sizes, int n_in,
                              void* d_out, int out_size) {
    const float* lbm  = (const float*)d_in[0];   // [N,3] float32
    const float* mass = (const float*)d_in[1];   // [N]   float32
    const float* lf   = (const float*)d_in[2];   // [51]  float32
    float* out = (float*)d_out;                  // [90,20,6] float32

    int n = in_sizes[1];
    int grid = (n + PART_PER_BLOCK - 1) / PART_PER_BLOCK;
    if (grid < 1) grid = 1;

    hist_kernel<<<grid, THREADS>>>(lbm, mass, n);

    {
        cudaLaunchConfig_t cfg = {};
        cfg.gridDim  = dim3(CONV_BLOCKS, 1, 1);
        cfg.blockDim = dim3(THREADS, 1, 1);
        cfg.dynamicSmemBytes = 0;
        cfg.stream = 0;
        cudaLaunchAttribute attrs[1];
        attrs[0].id = cudaLaunchAttributeProgrammaticStreamSerialization;
        attrs[0].val.programmaticStreamSerializationAllowed = 1;
        cfg.attrs = attrs;
        cfg.numAttrs = 1;
        cudaLaunchKernelEx(&cfg, conv_zero_kernel, lf, out);
    }
}